// round 3
// baseline (speedup 1.0000x reference)
#include <cuda_runtime.h>

// Problem: CtcBoundaryLossV3  — fused single-launch version.
// Inputs (metadata order):
//   d_in[0] alpha          float32  [B, T]
//   d_in[1] ctc_log_probs  float32  [B, T, V]
//   d_in[2] mask           float32  [B, T]
//   d_in[3] text_length    int32    [B]
// Output: float32 scalar.

#define SPLIT 8
#define MAXB  32        // B=16; warp-finalize supports up to 32

#define LOG_THR 1.0986122886681098f   // log(3.0)

__device__ float        g_psum[MAXB * SPLIT];
__device__ int          g_pcnt[MAXB * SPLIT];
__device__ unsigned int g_ticket = 0;   // reset to 0 by last block every call

__global__ void ctc_fused_kernel(const float* __restrict__ alpha,
                                 const float* __restrict__ ctc,
                                 const float* __restrict__ mask,
                                 const int*   __restrict__ tlen,
                                 float* __restrict__ out,
                                 int B, int T, int V, int chunkLen) {
    const int bid   = blockIdx.x;          // 0 .. B*SPLIT-1
    const int b     = bid / SPLIT;
    const int chunk = bid % SPLIT;
    const int t0    = chunk * chunkLen;
    const int tEnd  = min(t0 + chunkLen, T);

    // ---- Phase 1: partial reduction over this (batch, chunk) ----
    float lsum = 0.0f;
    int   lcnt = 0;
    const size_t rowBase = (size_t)b * (size_t)T;

    for (int t = t0 + threadIdx.x; t < tEnd; t += blockDim.x) {
        const size_t idx = rowBase + (size_t)t;
        float a  = alpha[idx];
        float mk = mask[idx];
        float bl = ctc[idx * (size_t)V];      // blank column (index 0)
        lsum += a;
        lcnt += (((1.0f - bl) > LOG_THR) && (mk != 0.0f)) ? 1 : 0;
    }

    #pragma unroll
    for (int off = 16; off > 0; off >>= 1) {
        lsum += __shfl_down_sync(0xFFFFFFFFu, lsum, off);
        lcnt += __shfl_down_sync(0xFFFFFFFFu, lcnt, off);
    }

    __shared__ float s_sum[8];
    __shared__ int   s_cnt[8];
    __shared__ int   s_amLast;
    const int wid = threadIdx.x >> 5;
    const int lid = threadIdx.x & 31;
    if (lid == 0) { s_sum[wid] = lsum; s_cnt[wid] = lcnt; }
    __syncthreads();

    if (threadIdx.x == 0) {
        float tsum = 0.0f;
        int   tcnt = 0;
        const int nw = (blockDim.x + 31) >> 5;
        #pragma unroll
        for (int w = 0; w < 8; w++) {
            if (w < nw) { tsum += s_sum[w]; tcnt += s_cnt[w]; }
        }
        g_psum[b * SPLIT + chunk] = tsum;
        g_pcnt[b * SPLIT + chunk] = tcnt;
        __threadfence();
        unsigned int prev = atomicAdd(&g_ticket, 1u);
        s_amLast = (prev == gridDim.x - 1u);
    }
    __syncthreads();

    // ---- Phase 2: last block finalizes with one warp ----
    if (!s_amLast || threadIdx.x >= 32) return;

    const int lane = threadIdx.x;

    float rs = 0.0f;
    int   ns = 0;
    int   tl = 1;
    if (lane < B) {
        #pragma unroll
        for (int c = 0; c < SPLIT; c++) {
            rs += g_psum[lane * SPLIT + c];
            ns += g_pcnt[lane * SPLIT + c];
        }
        tl = tlen[lane];
    }

    // L = min( max_b len_i , max_b text_length )
    int len_i = (lane < B) ? ((ns >= 1) ? ns : 1) : 0;
    int tmx   = (lane < B) ? tl : 0;
    #pragma unroll
    for (int off = 16; off > 0; off >>= 1) {
        len_i = max(len_i, __shfl_xor_sync(0xFFFFFFFFu, len_i, off));
        tmx   = max(tmx,   __shfl_xor_sync(0xFFFFFFFFu, tmx,   off));
    }
    const int L = min(len_i, tmx);

    float ps = 0.0f;
    if (lane < B) {
        int m = min(tl, L);                 // m >= 1
        if (ns >= 1) {
            int k = min(ns, m);
            ps = (float)k * fabsf(rs - 1.0f) + (float)(m - k);
        } else {
            ps = (float)(m - 1);
        }
    }
    #pragma unroll
    for (int off = 16; off > 0; off >>= 1)
        ps += __shfl_xor_sync(0xFFFFFFFFu, ps, off);

    if (lane == 0) {
        out[0] = ps / (float)B;
        g_ticket = 0;                       // reset for next graph replay
    }
}

extern "C" void kernel_launch(void* const* d_in, const int* in_sizes, int n_in,
                              void* d_out, int out_size) {
    const float* alpha = (const float*)d_in[0];
    const float* ctc   = (const float*)d_in[1];
    const float* mask  = (const float*)d_in[2];
    const int*   tlen  = (const int*)d_in[3];
    float*       out   = (float*)d_out;

    const int B  = in_sizes[3];
    const int BT = in_sizes[0];
    const int T  = BT / B;
    const int V  = in_sizes[1] / BT;
    const int chunkLen = (T + SPLIT - 1) / SPLIT;

    ctc_fused_kernel<<<B * SPLIT, 256>>>(alpha, ctc, mask, tlen, out,
                                         B, T, V, chunkLen);
}